// round 16
// baseline (speedup 1.0000x reference)
#include <cuda_runtime.h>
#include <cuda_bf16.h>
#include <math.h>

#define BB 32
#define NN 8192
#define NC 256
#define NP 32
#define MTOT (BB * NC)          // 8192 patches

// ---------------- scratch (device globals; no allocation allowed) ----------
__device__ float    g_centers[BB * NC * 3];
__device__ float    g_local  [MTOT * NP * 3];
__device__ float    g_cmean  [MTOT * 3];
__device__ unsigned g_scale_bits;
__device__ float    g_codeT [256 * MTOT];      // code transposed [c][m]
__device__ float    g_base1 [MTOT * 256];      // [m][c]
__device__ float    g_base2 [MTOT * 256];      // [m][c]
// pre-packed bf16x2 weights (word = (bf16(W[2k2][n]), bf16(W[2k2+1][n])))
__device__ unsigned g_We2p[64 * 256];          // We2  [128k][256n]
__device__ unsigned g_W1ap[128 * 256];         // Wf1a [256k][256n] (rows 0..255)
__device__ unsigned g_W2ap[128 * 256];         // Wf2a [256k][256n] (rows 0..255)
__device__ unsigned g_W1bp[128 * 128];         // Wf1b [256k][128n]
__device__ unsigned g_W2bp[128 * 128];         // Wf2b [256k][128n]

// ---------------- bf16 mma helpers ------------------------------------------
__device__ __forceinline__ unsigned pack_bf16x2(float lo, float hi) {
    unsigned r;
    asm("cvt.rn.bf16x2.f32 %0, %1, %2;" : "=r"(r) : "f"(hi), "f"(lo));
    return r;
}
__device__ __forceinline__ void mma_bf16(float* d, const unsigned* a,
                                         unsigned b0, unsigned b1) {
    asm volatile(
        "mma.sync.aligned.m16n8k16.row.col.f32.bf16.bf16.f32 "
        "{%0,%1,%2,%3}, {%4,%5,%6,%7}, {%8,%9}, {%0,%1,%2,%3};"
        : "+f"(d[0]), "+f"(d[1]), "+f"(d[2]), "+f"(d[3])
        : "r"(a[0]), "r"(a[1]), "r"(a[2]), "r"(a[3]), "r"(b0), "r"(b1));
}
// ldmatrix x4: returns A-frags m0..m3 in required mma order (1 op vs 4 LDS)
__device__ __forceinline__ void ldmatrix_x4(unsigned* a, unsigned saddr) {
    asm volatile("ldmatrix.sync.aligned.m8n8.x4.shared.b16 {%0,%1,%2,%3}, [%4];"
        : "=r"(a[0]), "=r"(a[1]), "=r"(a[2]), "=r"(a[3]) : "r"(saddr));
}
__device__ __forceinline__ unsigned smem_u32(const void* p) {
    return (unsigned)__cvta_generic_to_shared(p);
}

// ============================================================================
// K0: pre-pack MMA weights to bf16x2 word layout (once per launch, ~5us).
// ============================================================================
__global__ __launch_bounds__(256)
void pack_kernel(const float* __restrict__ We2,
                 const float* __restrict__ Wf1a, const float* __restrict__ Wf2a,
                 const float* __restrict__ Wf1b, const float* __restrict__ Wf2b)
{
    const int t = blockIdx.x * 256 + threadIdx.x;
    const float* src; unsigned* dst; int k2n, n;
    switch (blockIdx.y) {
        case 0:  src = We2;  dst = g_We2p; k2n = 64;  n = 256; break;
        case 1:  src = Wf1a; dst = g_W1ap; k2n = 128; n = 256; break;
        case 2:  src = Wf2a; dst = g_W2ap; k2n = 128; n = 256; break;
        case 3:  src = Wf1b; dst = g_W1bp; k2n = 128; n = 128; break;
        default: src = Wf2b; dst = g_W2bp; k2n = 128; n = 128; break;
    }
    if (t < k2n * n) {
        const int k2 = t / n, j = t - k2 * n;
        dst[t] = pack_bf16x2(src[(2 * k2) * n + j], src[(2 * k2 + 1) * n + j]);
    }
}

// ============================================================================
// K1: FPS — round-14 proven shape. Exact jnp.argmax semantics; distance
// arithmetic replicates the reference exactly (no FMA contraction).
// ============================================================================
__global__ __launch_bounds__(1024, 1)
void fps_kernel(const float* __restrict__ data)
{
    extern __shared__ float sm[];
    float* sx = sm;
    float* sy = sm + NN;
    float* sz = sm + 2 * NN;
    __shared__ unsigned long long skeys[32];
    __shared__ unsigned long long sres;

    const int b = blockIdx.x;
    const int t = threadIdx.x;
    const int wid = t >> 5, lane = t & 31;
    if (b == 0 && t == 0) g_scale_bits = 0u;   // reset every launch (graph replay safe)

    const float* dp = data + (size_t)b * 3 * NN;
    for (int n = t; n < NN; n += 1024) {
        sx[n] = dp[n];
        sy[n] = dp[NN + n];
        sz[n] = dp[2 * NN + n];
    }
    __syncthreads();

    float rx[8], ry[8], rz[8], md[8];
    const int base = t * 8;
    #pragma unroll
    for (int j = 0; j < 8; j++) {
        rx[j] = sx[base + j];
        ry[j] = sy[base + j];
        rz[j] = sz[base + j];
        md[j] = 3.4e38f;
    }

    float px = sx[0], py = sy[0], pz = sz[0];
    if (t == 0) {
        float* c = g_centers + (size_t)(b * NC) * 3;
        c[0] = px; c[1] = py; c[2] = pz;
    }

    for (int i = 1; i < NC; i++) {
        float bv = -1.0f; int bi = base;
        #pragma unroll
        for (int j = 0; j < 8; j++) {
            float dx = __fadd_rn(rx[j], -px);
            float dy = __fadd_rn(ry[j], -py);
            float dz = __fadd_rn(rz[j], -pz);
            float d  = __fadd_rn(__fadd_rn(__fmul_rn(dx, dx), __fmul_rn(dy, dy)),
                                 __fmul_rn(dz, dz));
            float m  = fminf(md[j], d);
            md[j] = m;
            if (m > bv) { bv = m; bi = base + j; }
        }
        unsigned long long key =
            ((unsigned long long)__float_as_uint(bv) << 32) | (unsigned)(NN - 1 - bi);
        #pragma unroll
        for (int off = 16; off; off >>= 1) {
            unsigned long long o = __shfl_down_sync(0xFFFFFFFFu, key, off);
            if (o > key) key = o;
        }
        if (lane == 0) skeys[wid] = key;
        __syncthreads();
        if (t < 32) {
            unsigned long long k2 = skeys[t];
            #pragma unroll
            for (int off = 16; off; off >>= 1) {
                unsigned long long o = __shfl_down_sync(0xFFFFFFFFu, k2, off);
                if (o > k2) k2 = o;
            }
            if (t == 0) sres = k2;
        }
        __syncthreads();
        const unsigned long long kk = sres;
        const int sel = NN - 1 - (int)(kk & 0xFFFFFFFFull);
        px = sx[sel]; py = sy[sel]; pz = sz[sel];
        if (t == 0) {
            float* c = g_centers + (size_t)(b * NC + i) * 3;
            c[0] = px; c[1] = py; c[2] = pz;
        }
    }
}

// ============================================================================
// K2: kNN set of 32 — one warp per center, 8 centers/block, points in smem.
// Sorted-insertion top-32; lax.top_k tie semantics. (round-14 proven)
// ============================================================================
__global__ __launch_bounds__(256, 2)
void knn_kernel(const float* __restrict__ data, const int* __restrict__ perm)
{
    extern __shared__ float sp[];                    // [3*NN]
    const int warp = threadIdx.x >> 5;
    const int lane = threadIdx.x & 31;
    const int w  = blockIdx.x * 8 + warp;
    const int b  = w >> 8;
    const int ci = w & 255;
    const int p  = perm[ci];

    const float* dp = data + (size_t)b * 3 * NN;
    for (int i = threadIdx.x; i < 3 * NN / 4; i += 256)
        ((float4*)sp)[i] = ((const float4*)dp)[i];
    __syncthreads();
    const float* sx = sp, *sy = sp + NN, *sz = sp + 2 * NN;

    const float* cc = g_centers + (size_t)(b * NC + p) * 3;
    const float cx = cc[0], cy = cc[1], cz = cc[2];
    const float cs = (cx * cx + cy * cy) + cz * cz;

    float kd = 3.4e38f;          // sorted ascending across lanes
    int   ki = -1;
    float cm = 3.4e38f;          // = kd at lane 31

    for (int bse = 0; bse < NN; bse += 32) {
        const int n = bse + lane;
        const float px = sx[n], py = sy[n], pz = sz[n];
        const float ps  = (px * px + py * py) + pz * pz;
        const float dot = (cx * px + cy * py) + cz * pz;
        const float d = (cs + ps) - 2.0f * dot;

        unsigned m = __ballot_sync(0xFFFFFFFFu, d < cm);
        while (m) {
            const int src = __ffs(m) - 1; m &= m - 1;
            const float dc = __shfl_sync(0xFFFFFFFFu, d, src);
            if (dc < cm) {                       // strict: equal-to-max never enters
                const int pos = __popc(__ballot_sync(0xFFFFFFFFu, kd <= dc));
                const float skd = __shfl_up_sync(0xFFFFFFFFu, kd, 1);
                const int   ski = __shfl_up_sync(0xFFFFFFFFu, ki, 1);
                if (lane > pos)       { kd = skd; ki = ski; }
                else if (lane == pos) { kd = dc;  ki = bse + src; }
                cm = __shfl_sync(0xFFFFFFFFu, kd, 31);
            }
        }
    }

    const float nx = sx[ki], ny = sy[ki], nz = sz[ki];
    float sxx = nx, syy = ny, szz = nz;
    #pragma unroll
    for (int off = 16; off; off >>= 1) {
        sxx += __shfl_xor_sync(0xFFFFFFFFu, sxx, off);
        syy += __shfl_xor_sync(0xFFFFFFFFu, syy, off);
        szz += __shfl_xor_sync(0xFFFFFFFFu, szz, off);
    }
    const float mx = sxx * (1.0f / 32.0f);
    const float my = syy * (1.0f / 32.0f);
    const float mz = szz * (1.0f / 32.0f);
    const float lx = nx - mx, ly = ny - my, lz = nz - mz;
    const float ns = (lx * lx + ly * ly) + lz * lz;
    float wm = ns;
    #pragma unroll
    for (int off = 16; off; off >>= 1) wm = fmaxf(wm, __shfl_xor_sync(0xFFFFFFFFu, wm, off));
    if (lane == 0) atomicMax(&g_scale_bits, __float_as_uint(wm));

    float* lp = g_local + ((size_t)w * NP + lane) * 3;
    lp[0] = lx; lp[1] = ly; lp[2] = lz;
    if (lane < 3) g_cmean[(size_t)w * 3 + lane] = (lane == 0) ? mx : ((lane == 1) ? my : mz);
}

// ============================================================================
// K3a enc: 2 patches/block, bf16 MMA, B direct from pre-packed global,
// A-fragments via ldmatrix.x4 (4x fewer L1 ops on the A side).
// ============================================================================
__global__ __launch_bounds__(256, 2)
void enc_kernel(const float* __restrict__ We1, const float* __restrict__ be1,
                const float* __restrict__ be2)
{
    extern __shared__ float s[];
    __nv_bfloat16* h1A = (__nv_bfloat16*)s;        // [64][136] bf16 = 4352 fl
    float* xs          = s + 4352;                 // [64][3]        =  192 fl
    const int t  = threadIdx.x;
    const int m0 = blockIdx.x * 2;
    const float scale = sqrtf(__uint_as_float(g_scale_bits));

    if (t < 192) xs[t] = g_local[(size_t)blockIdx.x * 192 + t] / scale;
    __syncthreads();

    // enc1 (exact fp32): thread handles k-pair (2kp, 2kp+1), rows rh,rh+4,...
    {
        const int kp = t & 63;
        const int rh = t >> 6;
        const float2 w0 = *(const float2*)(We1 + 0 * 128 + 2 * kp);
        const float2 w1 = *(const float2*)(We1 + 1 * 128 + 2 * kp);
        const float2 w2 = *(const float2*)(We1 + 2 * 128 + 2 * kp);
        const float2 bb = *(const float2*)(be1 + 2 * kp);
        unsigned* h1w = (unsigned*)h1A;
        #pragma unroll
        for (int i = 0; i < 16; i++) {
            const int r = i * 4 + rh;
            const float x0 = xs[r * 3], x1 = xs[r * 3 + 1], x2 = xs[r * 3 + 2];
            const float v0 = fmaxf(x0 * w0.x + x1 * w1.x + x2 * w2.x + bb.x, 0.0f);
            const float v1 = fmaxf(x0 * w0.y + x1 * w1.y + x2 * w2.y + bb.y, 0.0f);
            h1w[r * 68 + kp] = pack_bf16x2(v0, v1);
        }
    }
    __syncthreads();

    const int lane = t & 31, g = lane >> 2, tig = lane & 3;
    const int wb = (t >> 5) * 32;              // warp's 32-column strip

    // ldmatrix per-lane address base: row = ((lane>>3)&1)*8 + (lane&7),
    // kword = (lane>>4)*4; stride 68 words.
    const int rowA = ((lane >> 3) & 1) * 8 + (lane & 7);
    const int kwA  = (lane >> 4) * 4;
    const unsigned aBase = smem_u32(h1A) + (unsigned)(rowA * 68 + kwA) * 4u;

    float d[4][4][4];
    #pragma unroll
    for (int mt = 0; mt < 4; mt++)
        #pragma unroll
        for (int nt = 0; nt < 4; nt++)
            #pragma unroll
            for (int j = 0; j < 4; j++) d[mt][nt][j] = 0.0f;

    #pragma unroll 2
    for (int sl = 0; sl < 8; sl++) {           // 8 k16-steps, B direct from L2
        unsigned a[4][4];
        #pragma unroll
        for (int mt = 0; mt < 4; mt++)
            ldmatrix_x4(a[mt], aBase + (unsigned)(mt * 1088 + sl * 8) * 4u);
        #pragma unroll
        for (int nt = 0; nt < 4; nt++) {
            const unsigned b0 = g_We2p[(sl * 8 + tig) * 256 + wb + nt * 8 + g];
            const unsigned b1 = g_We2p[(sl * 8 + tig + 4) * 256 + wb + nt * 8 + g];
            #pragma unroll
            for (int mt = 0; mt < 4; mt++) mma_bf16(d[mt][nt], a[mt], b0, b1);
        }
    }

    // epilogue: bias + relu (fp32), maxpool, shfl over g, transposed write
    #pragma unroll
    for (int nt = 0; nt < 4; nt++) {
        const int c0 = wb + nt * 8 + 2 * tig;
        const float bb0 = be2[c0], bb1 = be2[c0 + 1];
        float p00 = fmaxf(fmaxf(fmaxf(d[0][nt][0], d[0][nt][2]),
                                fmaxf(d[1][nt][0], d[1][nt][2])) + bb0, 0.0f);
        float p01 = fmaxf(fmaxf(fmaxf(d[0][nt][1], d[0][nt][3]),
                                fmaxf(d[1][nt][1], d[1][nt][3])) + bb1, 0.0f);
        float p10 = fmaxf(fmaxf(fmaxf(d[2][nt][0], d[2][nt][2]),
                                fmaxf(d[3][nt][0], d[3][nt][2])) + bb0, 0.0f);
        float p11 = fmaxf(fmaxf(fmaxf(d[2][nt][1], d[2][nt][3]),
                                fmaxf(d[3][nt][1], d[3][nt][3])) + bb1, 0.0f);
        #pragma unroll
        for (int off = 4; off <= 16; off <<= 1) {
            p00 = fmaxf(p00, __shfl_xor_sync(0xFFFFFFFFu, p00, off));
            p01 = fmaxf(p01, __shfl_xor_sync(0xFFFFFFFFu, p01, off));
            p10 = fmaxf(p10, __shfl_xor_sync(0xFFFFFFFFu, p10, off));
            p11 = fmaxf(p11, __shfl_xor_sync(0xFFFFFFFFu, p11, off));
        }
        if (g == 0) {
            *(float2*)(g_codeT + (size_t)c0 * MTOT + m0)       = make_float2(p00, p10);
            *(float2*)(g_codeT + (size_t)(c0 + 1) * MTOT + m0) = make_float2(p01, p11);
        }
    }
}

// ============================================================================
// K3b base: bf16 MMA, B direct from pre-packed global, A via ldmatrix.
// ============================================================================
__global__ __launch_bounds__(256, 2)
void base_kernel(const float* __restrict__ bf1a, const float* __restrict__ bf2a)
{
    extern __shared__ float s[];
    unsigned* cAw = (unsigned*)s;               // [64 m][132 w] = 8448 fl

    const int t  = threadIdx.x;
    const int m0 = blockIdx.x * 64;
    const int mat = blockIdx.y;
    const unsigned* Wp = mat ? g_W2ap : g_W1ap;
    const float* bv = mat ? bf2a : bf1a;
    float* dst = mat ? g_base2 : g_base1;

    // A build from codeT (packed bf16x2 words, stride 132)
    {
        const int mq  = t & 15;
        const int k2g = t >> 4;
        #pragma unroll
        for (int i = 0; i < 8; i++) {
            const int k2 = k2g + 16 * i;
            const float4 a = *(const float4*)(g_codeT + (size_t)(2 * k2) * MTOT + m0 + 4 * mq);
            const float4 b = *(const float4*)(g_codeT + (size_t)(2 * k2 + 1) * MTOT + m0 + 4 * mq);
            cAw[(4 * mq + 0) * 132 + k2] = pack_bf16x2(a.x, b.x);
            cAw[(4 * mq + 1) * 132 + k2] = pack_bf16x2(a.y, b.y);
            cAw[(4 * mq + 2) * 132 + k2] = pack_bf16x2(a.z, b.z);
            cAw[(4 * mq + 3) * 132 + k2] = pack_bf16x2(a.w, b.w);
        }
    }
    __syncthreads();

    const int lane = t & 31, g = lane >> 2, tig = lane & 3;
    const int wb = (t >> 5) * 32;

    const int rowA = ((lane >> 3) & 1) * 8 + (lane & 7);
    const int kwA  = (lane >> 4) * 4;
    const unsigned aBase = smem_u32(cAw) + (unsigned)(rowA * 132 + kwA) * 4u;

    float d[4][4][4];
    #pragma unroll
    for (int mt = 0; mt < 4; mt++)
        #pragma unroll
        for (int nt = 0; nt < 4; nt++)
            #pragma unroll
            for (int j = 0; j < 4; j++) d[mt][nt][j] = 0.0f;

    #pragma unroll 2
    for (int sl = 0; sl < 16; sl++) {          // 16 k16-steps, B direct
        unsigned a[4][4];
        #pragma unroll
        for (int mt = 0; mt < 4; mt++)
            ldmatrix_x4(a[mt], aBase + (unsigned)(mt * 2112 + sl * 8) * 4u);
        #pragma unroll
        for (int nt = 0; nt < 4; nt++) {
            const unsigned b0 = Wp[(sl * 8 + tig) * 256 + wb + nt * 8 + g];
            const unsigned b1 = Wp[(sl * 8 + tig + 4) * 256 + wb + nt * 8 + g];
            #pragma unroll
            for (int mt = 0; mt < 4; mt++) mma_bf16(d[mt][nt], a[mt], b0, b1);
        }
    }

    #pragma unroll
    for (int nt = 0; nt < 4; nt++) {
        const int c0 = wb + nt * 8 + 2 * tig;
        const float bb0 = bv[c0], bb1 = bv[c0 + 1];
        #pragma unroll
        for (int mt = 0; mt < 4; mt++) {
            const int r = mt * 16 + g;
            *(float2*)(dst + (size_t)(m0 + r) * 256 + c0) =
                make_float2(d[mt][nt][0] + bb0, d[mt][nt][1] + bb1);
            *(float2*)(dst + (size_t)(m0 + r + 8) * 256 + c0) =
                make_float2(d[mt][nt][2] + bb0, d[mt][nt][3] + bb1);
        }
    }
}

// ============================================================================
// K3c fold: 2 patches/block, 512 threads, occ 2, bf16 MMA; B direct from
// pre-packed global, A per-half rebuild + ldmatrix. fold1c/2c exact fp32.
// ============================================================================
__global__ __launch_bounds__(512, 2)
void fold_kernel(const float* __restrict__ grid_,
                 const float* __restrict__ Wf1a,
                 const float* __restrict__ bf1b,
                 const float* __restrict__ Wf1c, const float* __restrict__ bf1c,
                 const float* __restrict__ Wf2a,
                 const float* __restrict__ bf2b,
                 const float* __restrict__ Wf2c, const float* __restrict__ bf2c,
                 float* __restrict__ out)
{
    extern __shared__ float s[];
    __nv_bfloat16* hfA = (__nv_bfloat16*)s;        // [64][136] bf16 = 4352 fl
    float* hf2         = s + 4352;                 // [64 r][132] f32 = 8448 fl
    float* Wc1         = s + 12800;                // [384]
    float* Wc2         = s + 13184;                // [384]
    float* gx          = s + 13568;                // [32]
    float* gy          = s + 13600;                // [32]
    float* fv          = s + 13632;                // [192]
    float* cm          = s + 13824;                // [8] -> 13832 fl = 55328 B

    const int t = threadIdx.x;
    const int m0 = blockIdx.x * 2;
    const float scale = sqrtf(__uint_as_float(g_scale_bits));

    const int kp   = t & 63;       // k-pair within half
    const int rgrp = t >> 6;       // rows rgrp*8..+7
    const int pA   = rgrp >> 2;    // patch

    if (t < 384) { Wc1[t] = Wf1c[t]; Wc2[t] = Wf2c[t]; }
    if (t < 32) { gx[t] = grid_[2 * t]; gy[t] = grid_[2 * t + 1]; }
    if (t < 6)  cm[t] = g_cmean[(size_t)m0 * 3 + t];
    __syncthreads();

    const int lane = t & 31, g = lane >> 2, tig = lane & 3;
    const int wb = (t >> 5) * 8;               // warp's 8-column strip

    unsigned* h1w = (unsigned*)hfA;            // word view, stride 68
    const int rowA = ((lane >> 3) & 1) * 8 + (lane & 7);
    const int kwA  = (lane >> 4) * 4;
    const unsigned aBase = smem_u32(hfA) + (unsigned)(rowA * 68 + kwA) * 4u;

    #pragma unroll
    for (int stagei = 0; stagei < 2; stagei++) {
        const unsigned* Wp = stagei ? g_W2bp : g_W1bp;
        const float* bv = stagei ? bf2b : bf1b;

        float d[4][4];
        #pragma unroll
        for (int mt = 0; mt < 4; mt++)
            #pragma unroll
            for (int j = 0; j < 4; j++) d[mt][j] = 0.0f;

        #pragma unroll
        for (int h = 0; h < 2; h++) {
            // rebuild A for half h (packed bf16x2 stores)
            if (h) __syncthreads();            // prior half's MMA reads done
            {
                const int kg = h * 128 + 2 * kp;
                if (stagei == 0) {
                    const float2 bb = *(const float2*)(g_base1 + (size_t)(m0 + pA) * 256 + kg);
                    const float2 w0 = *(const float2*)(Wf1a + 256 * 256 + kg);
                    const float2 w1 = *(const float2*)(Wf1a + 257 * 256 + kg);
                    #pragma unroll
                    for (int i = 0; i < 8; i++) {
                        const int r  = rgrp * 8 + i;
                        const int rr = r & 31;
                        const float v0 = fmaxf(bb.x + gx[rr] * w0.x + gy[rr] * w1.x, 0.0f);
                        const float v1 = fmaxf(bb.y + gx[rr] * w0.y + gy[rr] * w1.y, 0.0f);
                        h1w[r * 68 + kp] = pack_bf16x2(v0, v1);
                    }
                } else {
                    const float2 bb = *(const float2*)(g_base2 + (size_t)(m0 + pA) * 256 + kg);
                    const float2 w0 = *(const float2*)(Wf2a + 256 * 256 + kg);
                    const float2 w1 = *(const float2*)(Wf2a + 257 * 256 + kg);
                    const float2 w2 = *(const float2*)(Wf2a + 258 * 256 + kg);
                    #pragma unroll
                    for (int i = 0; i < 8; i++) {
                        const int r = rgrp * 8 + i;
                        const float f0 = fv[r * 3], f1 = fv[r * 3 + 1], f2 = fv[r * 3 + 2];
                        const float v0 = fmaxf(bb.x + f0 * w0.x + f1 * w1.x + f2 * w2.x, 0.0f);
                        const float v1 = fmaxf(bb.y + f0 * w0.y + f1 * w1.y + f2 * w2.y, 0.0f);
                        h1w[r * 68 + kp] = pack_bf16x2(v0, v1);
                    }
                }
            }
            __syncthreads();                   // A ready

            // 8 k16-steps over this half; B direct from L2, A via ldmatrix
            #pragma unroll 2
            for (int ks = 0; ks < 8; ks++) {
                const int k2r = h * 64 + ks * 8;       // global k2 row base
                const unsigned b0 = Wp[(k2r + tig) * 128 + wb + g];
                const unsigned b1 = Wp[(k2r + tig + 4) * 128 + wb + g];
                #pragma unroll
                for (int mt = 0; mt < 4; mt++) {
                    unsigned a[4];
                    ldmatrix_x4(a, aBase + (unsigned)(mt * 1088 + ks * 8) * 4u);
                    mma_bf16(d[mt], a, b0, b1);
                }
            }
        }

        // epilogue: bias + relu -> hf2[64 r][132]  (exact fp32)
        {
            const int col = wb + 2 * tig;
            const float bb0 = bv[col], bb1 = bv[col + 1];
            #pragma unroll
            for (int mt = 0; mt < 4; mt++) {
                const int r = mt * 16 + g;
                *(float2*)(hf2 + r * 132 + col) =
                    make_float2(fmaxf(d[mt][0] + bb0, 0.0f),
                                fmaxf(d[mt][1] + bb1, 0.0f));
                *(float2*)(hf2 + (r + 8) * 132 + col) =
                    make_float2(fmaxf(d[mt][2] + bb0, 0.0f),
                                fmaxf(d[mt][3] + bb1, 0.0f));
            }
        }
        __syncthreads();

        if (stagei == 0) {
            // fold1c: fv[r][q] = hf2[r]·Wf1c[:,q] + bf1c[q]  (exact fp32)
            if (t < 192) {
                const int r = t / 3, q = t - (t / 3) * 3;
                float acc = bf1c[q];
                #pragma unroll 8
                for (int k = 0; k < 128; k++) acc += hf2[r * 132 + k] * Wc1[k * 3 + q];
                fv[t] = acc;
            }
            __syncthreads();
        } else {
            // fold2c + output (exact fp32)
            if (t < 192) {
                const int r = t / 3, q = t - (t / 3) * 3;
                const int p = r >> 5, rr = r & 31;
                float acc = bf2c[q];
                #pragma unroll 8
                for (int k = 0; k < 128; k++) acc += hf2[r * 132 + k] * Wc2[k * 3 + q];
                out[(size_t)(m0 + p) * 96 + rr * 3 + q] = acc * scale + cm[p * 3 + q];
            }
        }
    }
}

// ============================================================================
extern "C" void kernel_launch(void* const* d_in, const int* in_sizes, int n_in,
                              void* d_out, int out_size)
{
    (void)in_sizes; (void)n_in; (void)out_size;
    const float* data = (const float*)d_in[0];
    const int*   perm = (const int*)  d_in[1];
    const float* grid = (const float*)d_in[2];
    const float* We1  = (const float*)d_in[3];
    const float* be1  = (const float*)d_in[4];
    const float* We2  = (const float*)d_in[5];
    const float* be2  = (const float*)d_in[6];
    const float* Wf1a = (const float*)d_in[7];
    const float* bf1a = (const float*)d_in[8];
    const float* Wf1b = (const float*)d_in[9];
    const float* bf1b = (const float*)d_in[10];
    const float* Wf1c = (const float*)d_in[11];
    const float* bf1c = (const float*)d_in[12];
    const float* Wf2a = (const float*)d_in[13];
    const float* bf2a = (const float*)d_in[14];
    const float* Wf2b = (const float*)d_in[15];
    const float* bf2b = (const float*)d_in[16];
    const float* Wf2c = (const float*)d_in[17];
    const float* bf2c = (const float*)d_in[18];
    float* out = (float*)d_out;

    const int fps_smem  = 3 * NN * sizeof(float);      // 98304
    const int knn_smem  = 3 * NN * sizeof(float);      // 98304
    const int enc_smem  = 4544  * sizeof(float);       // 18176
    const int base_smem = 8448  * sizeof(float);       // 33792
    const int fold_smem = 13832 * sizeof(float);       // 55328
    cudaFuncSetAttribute(fps_kernel,  cudaFuncAttributeMaxDynamicSharedMemorySize, fps_smem);
    cudaFuncSetAttribute(knn_kernel,  cudaFuncAttributeMaxDynamicSharedMemorySize, knn_smem);
    cudaFuncSetAttribute(enc_kernel,  cudaFuncAttributeMaxDynamicSharedMemorySize, enc_smem);
    cudaFuncSetAttribute(base_kernel, cudaFuncAttributeMaxDynamicSharedMemorySize, base_smem);
    cudaFuncSetAttribute(fold_kernel, cudaFuncAttributeMaxDynamicSharedMemorySize, fold_smem);

    pack_kernel<<<dim3(128, 5), 256>>>(We2, Wf1a, Wf2a, Wf1b, Wf2b);
    fps_kernel <<<BB, 1024, fps_smem>>>(data);
    knn_kernel <<<(BB * NC) / 8, 256, knn_smem>>>(data, perm);
    enc_kernel <<<MTOT / 2, 256, enc_smem>>>(We1, be1, be2);
    base_kernel<<<dim3(MTOT / 64, 2), 256, base_smem>>>(bf1a, bf2a);
    fold_kernel<<<MTOT / 2, 512, fold_smem>>>(grid, Wf1a, bf1b, Wf1c, bf1c,
                                              Wf2a, bf2b, Wf2c, bf2c, out);
}

// round 17
// speedup vs baseline: 1.0977x; 1.0977x over previous
#include <cuda_runtime.h>
#include <cuda_bf16.h>
#include <math.h>

#define BB 32
#define NN 8192
#define NC 256
#define NP 32
#define MTOT (BB * NC)          // 8192 patches

// ---------------- scratch (device globals; no allocation allowed) ----------
__device__ float    g_centers[BB * NC * 3];
__device__ float    g_local  [MTOT * NP * 3];
__device__ float    g_cmean  [MTOT * 3];
__device__ unsigned g_scale_bits;
__device__ float    g_codeT [256 * MTOT];      // code transposed [c][m]
__device__ float    g_base1 [MTOT * 256];      // [m][c]
__device__ float    g_base2 [MTOT * 256];      // [m][c]
// FRAGMENT-MAJOR pre-packed bf16x2 weights:
// word[((s*(N/8)+j)*32 + lane)*2 + c] = pack(W[2k2][n], W[2k2+1][n])
//   with k2 = s*8 + (lane&3) + c*4, n = j*8 + (lane>>2)
// -> per (k-step, n8-group) each lane LDG.64s its (b0,b1) pair, 32 lanes
//    cover 256 contiguous bytes = 2 L1 lines (was 4 lines per scalar LDG).
__device__ unsigned g_We2p[64 * 256];          // We2  K=128, N=256
__device__ unsigned g_W1ap[128 * 256];         // Wf1a K=256, N=256 (rows 0..255)
__device__ unsigned g_W2ap[128 * 256];         // Wf2a K=256, N=256 (rows 0..255)
__device__ unsigned g_W1bp[128 * 128];         // Wf1b K=256, N=128
__device__ unsigned g_W2bp[128 * 128];         // Wf2b K=256, N=128

// ---------------- bf16 mma helpers ------------------------------------------
__device__ __forceinline__ unsigned pack_bf16x2(float lo, float hi) {
    unsigned r;
    asm("cvt.rn.bf16x2.f32 %0, %1, %2;" : "=r"(r) : "f"(hi), "f"(lo));
    return r;
}
__device__ __forceinline__ void mma_bf16(float* d, const unsigned* a,
                                         unsigned b0, unsigned b1) {
    asm volatile(
        "mma.sync.aligned.m16n8k16.row.col.f32.bf16.bf16.f32 "
        "{%0,%1,%2,%3}, {%4,%5,%6,%7}, {%8,%9}, {%0,%1,%2,%3};"
        : "+f"(d[0]), "+f"(d[1]), "+f"(d[2]), "+f"(d[3])
        : "r"(a[0]), "r"(a[1]), "r"(a[2]), "r"(a[3]), "r"(b0), "r"(b1));
}

// ============================================================================
// K0: pre-pack MMA weights to FRAGMENT-MAJOR bf16x2 layout (once, ~5us).
// ============================================================================
__global__ __launch_bounds__(256)
void pack_kernel(const float* __restrict__ We2,
                 const float* __restrict__ Wf1a, const float* __restrict__ Wf2a,
                 const float* __restrict__ Wf1b, const float* __restrict__ Wf2b)
{
    const int t = blockIdx.x * 256 + threadIdx.x;
    const float* src; unsigned* dst; int k2n, n;
    switch (blockIdx.y) {
        case 0:  src = We2;  dst = g_We2p; k2n = 64;  n = 256; break;
        case 1:  src = Wf1a; dst = g_W1ap; k2n = 128; n = 256; break;
        case 2:  src = Wf2a; dst = g_W2ap; k2n = 128; n = 256; break;
        case 3:  src = Wf1b; dst = g_W1bp; k2n = 128; n = 128; break;
        default: src = Wf2b; dst = g_W2bp; k2n = 128; n = 128; break;
    }
    if (t < k2n * n) {
        const int c    = t & 1;
        const int lane = (t >> 1) & 31;
        const int nj   = n >> 3;                  // n8 groups
        const int j    = (t >> 6) % nj;
        const int s    = (t >> 6) / nj;           // k16-step
        const int tig  = lane & 3, g = lane >> 2;
        const int k2   = s * 8 + tig + c * 4;
        const int nn   = j * 8 + g;
        dst[t] = pack_bf16x2(src[(2 * k2) * n + nn], src[(2 * k2 + 1) * n + nn]);
    }
}

// ============================================================================
// K1: FPS — round-14 proven shape. Exact jnp.argmax semantics; distance
// arithmetic replicates the reference exactly (no FMA contraction).
// ============================================================================
__global__ __launch_bounds__(1024, 1)
void fps_kernel(const float* __restrict__ data)
{
    extern __shared__ float sm[];
    float* sx = sm;
    float* sy = sm + NN;
    float* sz = sm + 2 * NN;
    __shared__ unsigned long long skeys[32];
    __shared__ unsigned long long sres;

    const int b = blockIdx.x;
    const int t = threadIdx.x;
    const int wid = t >> 5, lane = t & 31;
    if (b == 0 && t == 0) g_scale_bits = 0u;   // reset every launch (graph replay safe)

    const float* dp = data + (size_t)b * 3 * NN;
    for (int n = t; n < NN; n += 1024) {
        sx[n] = dp[n];
        sy[n] = dp[NN + n];
        sz[n] = dp[2 * NN + n];
    }
    __syncthreads();

    float rx[8], ry[8], rz[8], md[8];
    const int base = t * 8;
    #pragma unroll
    for (int j = 0; j < 8; j++) {
        rx[j] = sx[base + j];
        ry[j] = sy[base + j];
        rz[j] = sz[base + j];
        md[j] = 3.4e38f;
    }

    float px = sx[0], py = sy[0], pz = sz[0];
    if (t == 0) {
        float* c = g_centers + (size_t)(b * NC) * 3;
        c[0] = px; c[1] = py; c[2] = pz;
    }

    for (int i = 1; i < NC; i++) {
        float bv = -1.0f; int bi = base;
        #pragma unroll
        for (int j = 0; j < 8; j++) {
            float dx = __fadd_rn(rx[j], -px);
            float dy = __fadd_rn(ry[j], -py);
            float dz = __fadd_rn(rz[j], -pz);
            float d  = __fadd_rn(__fadd_rn(__fmul_rn(dx, dx), __fmul_rn(dy, dy)),
                                 __fmul_rn(dz, dz));
            float m  = fminf(md[j], d);
            md[j] = m;
            if (m > bv) { bv = m; bi = base + j; }
        }
        unsigned long long key =
            ((unsigned long long)__float_as_uint(bv) << 32) | (unsigned)(NN - 1 - bi);
        #pragma unroll
        for (int off = 16; off; off >>= 1) {
            unsigned long long o = __shfl_down_sync(0xFFFFFFFFu, key, off);
            if (o > key) key = o;
        }
        if (lane == 0) skeys[wid] = key;
        __syncthreads();
        if (t < 32) {
            unsigned long long k2 = skeys[t];
            #pragma unroll
            for (int off = 16; off; off >>= 1) {
                unsigned long long o = __shfl_down_sync(0xFFFFFFFFu, k2, off);
                if (o > k2) k2 = o;
            }
            if (t == 0) sres = k2;
        }
        __syncthreads();
        const unsigned long long kk = sres;
        const int sel = NN - 1 - (int)(kk & 0xFFFFFFFFull);
        px = sx[sel]; py = sy[sel]; pz = sz[sel];
        if (t == 0) {
            float* c = g_centers + (size_t)(b * NC + i) * 3;
            c[0] = px; c[1] = py; c[2] = pz;
        }
    }
}

// ============================================================================
// K2: kNN set of 32 — one warp per center, 8 centers/block, points in smem.
// Sorted-insertion top-32; lax.top_k tie semantics. (round-14 proven)
// ============================================================================
__global__ __launch_bounds__(256, 2)
void knn_kernel(const float* __restrict__ data, const int* __restrict__ perm)
{
    extern __shared__ float sp[];                    // [3*NN]
    const int warp = threadIdx.x >> 5;
    const int lane = threadIdx.x & 31;
    const int w  = blockIdx.x * 8 + warp;
    const int b  = w >> 8;
    const int ci = w & 255;
    const int p  = perm[ci];

    const float* dp = data + (size_t)b * 3 * NN;
    for (int i = threadIdx.x; i < 3 * NN / 4; i += 256)
        ((float4*)sp)[i] = ((const float4*)dp)[i];
    __syncthreads();
    const float* sx = sp, *sy = sp + NN, *sz = sp + 2 * NN;

    const float* cc = g_centers + (size_t)(b * NC + p) * 3;
    const float cx = cc[0], cy = cc[1], cz = cc[2];
    const float cs = (cx * cx + cy * cy) + cz * cz;

    float kd = 3.4e38f;          // sorted ascending across lanes
    int   ki = -1;
    float cm = 3.4e38f;          // = kd at lane 31

    for (int bse = 0; bse < NN; bse += 32) {
        const int n = bse + lane;
        const float px = sx[n], py = sy[n], pz = sz[n];
        const float ps  = (px * px + py * py) + pz * pz;
        const float dot = (cx * px + cy * py) + cz * pz;
        const float d = (cs + ps) - 2.0f * dot;

        unsigned m = __ballot_sync(0xFFFFFFFFu, d < cm);
        while (m) {
            const int src = __ffs(m) - 1; m &= m - 1;
            const float dc = __shfl_sync(0xFFFFFFFFu, d, src);
            if (dc < cm) {                       // strict: equal-to-max never enters
                const int pos = __popc(__ballot_sync(0xFFFFFFFFu, kd <= dc));
                const float skd = __shfl_up_sync(0xFFFFFFFFu, kd, 1);
                const int   ski = __shfl_up_sync(0xFFFFFFFFu, ki, 1);
                if (lane > pos)       { kd = skd; ki = ski; }
                else if (lane == pos) { kd = dc;  ki = bse + src; }
                cm = __shfl_sync(0xFFFFFFFFu, kd, 31);
            }
        }
    }

    const float nx = sx[ki], ny = sy[ki], nz = sz[ki];
    float sxx = nx, syy = ny, szz = nz;
    #pragma unroll
    for (int off = 16; off; off >>= 1) {
        sxx += __shfl_xor_sync(0xFFFFFFFFu, sxx, off);
        syy += __shfl_xor_sync(0xFFFFFFFFu, syy, off);
        szz += __shfl_xor_sync(0xFFFFFFFFu, szz, off);
    }
    const float mx = sxx * (1.0f / 32.0f);
    const float my = syy * (1.0f / 32.0f);
    const float mz = szz * (1.0f / 32.0f);
    const float lx = nx - mx, ly = ny - my, lz = nz - mz;
    const float ns = (lx * lx + ly * ly) + lz * lz;
    float wm = ns;
    #pragma unroll
    for (int off = 16; off; off >>= 1) wm = fmaxf(wm, __shfl_xor_sync(0xFFFFFFFFu, wm, off));
    if (lane == 0) atomicMax(&g_scale_bits, __float_as_uint(wm));

    float* lp = g_local + ((size_t)w * NP + lane) * 3;
    lp[0] = lx; lp[1] = ly; lp[2] = lz;
    if (lane < 3) g_cmean[(size_t)w * 3 + lane] = (lane == 0) ? mx : ((lane == 1) ? my : mz);
}

// ============================================================================
// K3a enc: 2 patches/block, bf16 MMA, B via fragment-major LDG.64 (2 lines/
// fetch instead of 4 lines/word), A scalar LDS (r15-proven).
// ============================================================================
__global__ __launch_bounds__(256, 2)
void enc_kernel(const float* __restrict__ We1, const float* __restrict__ be1,
                const float* __restrict__ be2)
{
    extern __shared__ float s[];
    __nv_bfloat16* h1A = (__nv_bfloat16*)s;        // [64][136] bf16 = 4352 fl
    float* xs          = s + 4352;                 // [64][3]        =  192 fl
    const int t  = threadIdx.x;
    const int m0 = blockIdx.x * 2;
    const float scale = sqrtf(__uint_as_float(g_scale_bits));

    if (t < 192) xs[t] = g_local[(size_t)blockIdx.x * 192 + t] / scale;
    __syncthreads();

    // enc1 (exact fp32): thread handles k-pair (2kp, 2kp+1), rows rh,rh+4,...
    {
        const int kp = t & 63;
        const int rh = t >> 6;
        const float2 w0 = *(const float2*)(We1 + 0 * 128 + 2 * kp);
        const float2 w1 = *(const float2*)(We1 + 1 * 128 + 2 * kp);
        const float2 w2 = *(const float2*)(We1 + 2 * 128 + 2 * kp);
        const float2 bb = *(const float2*)(be1 + 2 * kp);
        unsigned* h1w = (unsigned*)h1A;
        #pragma unroll
        for (int i = 0; i < 16; i++) {
            const int r = i * 4 + rh;
            const float x0 = xs[r * 3], x1 = xs[r * 3 + 1], x2 = xs[r * 3 + 2];
            const float v0 = fmaxf(x0 * w0.x + x1 * w1.x + x2 * w2.x + bb.x, 0.0f);
            const float v1 = fmaxf(x0 * w0.y + x1 * w1.y + x2 * w2.y + bb.y, 0.0f);
            h1w[r * 68 + kp] = pack_bf16x2(v0, v1);
        }
    }
    __syncthreads();

    const int lane = t & 31, g = lane >> 2, tig = lane & 3;
    const int wb = (t >> 5) * 32;              // warp's 32-column strip
    const int jb = (t >> 5) * 4;               // warp's n8-group base

    float d[4][4][4];
    #pragma unroll
    for (int mt = 0; mt < 4; mt++)
        #pragma unroll
        for (int nt = 0; nt < 4; nt++)
            #pragma unroll
            for (int j = 0; j < 4; j++) d[mt][nt][j] = 0.0f;

    #pragma unroll 2
    for (int sl = 0; sl < 8; sl++) {           // 8 k16-steps, B direct from L2
        unsigned a[4][4];
        #pragma unroll
        for (int mt = 0; mt < 4; mt++) {
            const unsigned* ap = (const unsigned*)h1A + (mt * 16 + g) * 68 + sl * 8 + tig;
            a[mt][0] = ap[0];
            a[mt][1] = ap[8 * 68];
            a[mt][2] = ap[4];
            a[mt][3] = ap[8 * 68 + 4];
        }
        #pragma unroll
        for (int nt = 0; nt < 4; nt++) {
            const uint2 bb = *(const uint2*)(g_We2p +
                (((size_t)(sl * 32 + jb + nt) * 32 + lane) * 2));
            #pragma unroll
            for (int mt = 0; mt < 4; mt++) mma_bf16(d[mt][nt], a[mt], bb.x, bb.y);
        }
    }

    // epilogue: bias + relu (fp32), maxpool, shfl over g, transposed write
    #pragma unroll
    for (int nt = 0; nt < 4; nt++) {
        const int c0 = wb + nt * 8 + 2 * tig;
        const float bb0 = be2[c0], bb1 = be2[c0 + 1];
        float p00 = fmaxf(fmaxf(fmaxf(d[0][nt][0], d[0][nt][2]),
                                fmaxf(d[1][nt][0], d[1][nt][2])) + bb0, 0.0f);
        float p01 = fmaxf(fmaxf(fmaxf(d[0][nt][1], d[0][nt][3]),
                                fmaxf(d[1][nt][1], d[1][nt][3])) + bb1, 0.0f);
        float p10 = fmaxf(fmaxf(fmaxf(d[2][nt][0], d[2][nt][2]),
                                fmaxf(d[3][nt][0], d[3][nt][2])) + bb0, 0.0f);
        float p11 = fmaxf(fmaxf(fmaxf(d[2][nt][1], d[2][nt][3]),
                                fmaxf(d[3][nt][1], d[3][nt][3])) + bb1, 0.0f);
        #pragma unroll
        for (int off = 4; off <= 16; off <<= 1) {
            p00 = fmaxf(p00, __shfl_xor_sync(0xFFFFFFFFu, p00, off));
            p01 = fmaxf(p01, __shfl_xor_sync(0xFFFFFFFFu, p01, off));
            p10 = fmaxf(p10, __shfl_xor_sync(0xFFFFFFFFu, p10, off));
            p11 = fmaxf(p11, __shfl_xor_sync(0xFFFFFFFFu, p11, off));
        }
        if (g == 0) {
            *(float2*)(g_codeT + (size_t)c0 * MTOT + m0)       = make_float2(p00, p10);
            *(float2*)(g_codeT + (size_t)(c0 + 1) * MTOT + m0) = make_float2(p01, p11);
        }
    }
}

// ============================================================================
// K3b base: bf16 MMA, B via fragment-major LDG.64, A scalar LDS.
// ============================================================================
__global__ __launch_bounds__(256, 2)
void base_kernel(const float* __restrict__ bf1a, const float* __restrict__ bf2a)
{
    extern __shared__ float s[];
    unsigned* cAw = (unsigned*)s;               // [64 m][132 w] = 8448 fl

    const int t  = threadIdx.x;
    const int m0 = blockIdx.x * 64;
    const int mat = blockIdx.y;
    const unsigned* Wp = mat ? g_W2ap : g_W1ap;
    const float* bv = mat ? bf2a : bf1a;
    float* dst = mat ? g_base2 : g_base1;

    // A build from codeT (packed bf16x2 words, stride 132)
    {
        const int mq  = t & 15;
        const int k2g = t >> 4;
        #pragma unroll
        for (int i = 0; i < 8; i++) {
            const int k2 = k2g + 16 * i;
            const float4 a = *(const float4*)(g_codeT + (size_t)(2 * k2) * MTOT + m0 + 4 * mq);
            const float4 b = *(const float4*)(g_codeT + (size_t)(2 * k2 + 1) * MTOT + m0 + 4 * mq);
            cAw[(4 * mq + 0) * 132 + k2] = pack_bf16x2(a.x, b.x);
            cAw[(4 * mq + 1) * 132 + k2] = pack_bf16x2(a.y, b.y);
            cAw[(4 * mq + 2) * 132 + k2] = pack_bf16x2(a.z, b.z);
            cAw[(4 * mq + 3) * 132 + k2] = pack_bf16x2(a.w, b.w);
        }
    }
    __syncthreads();

    const int lane = t & 31, g = lane >> 2, tig = lane & 3;
    const int wb = (t >> 5) * 32;
    const int jb = (t >> 5) * 4;

    float d[4][4][4];
    #pragma unroll
    for (int mt = 0; mt < 4; mt++)
        #pragma unroll
        for (int nt = 0; nt < 4; nt++)
            #pragma unroll
            for (int j = 0; j < 4; j++) d[mt][nt][j] = 0.0f;

    #pragma unroll 2
    for (int sl = 0; sl < 16; sl++) {          // 16 k16-steps, B direct
        unsigned a[4][4];
        #pragma unroll
        for (int mt = 0; mt < 4; mt++) {
            const unsigned* ap = cAw + (mt * 16 + g) * 132 + sl * 8 + tig;
            a[mt][0] = ap[0];
            a[mt][1] = ap[8 * 132];
            a[mt][2] = ap[4];
            a[mt][3] = ap[8 * 132 + 4];
        }
        #pragma unroll
        for (int nt = 0; nt < 4; nt++) {
            const uint2 bb = *(const uint2*)(Wp +
                (((size_t)(sl * 32 + jb + nt) * 32 + lane) * 2));
            #pragma unroll
            for (int mt = 0; mt < 4; mt++) mma_bf16(d[mt][nt], a[mt], bb.x, bb.y);
        }
    }

    #pragma unroll
    for (int nt = 0; nt < 4; nt++) {
        const int c0 = wb + nt * 8 + 2 * tig;
        const float bb0 = bv[c0], bb1 = bv[c0 + 1];
        #pragma unroll
        for (int mt = 0; mt < 4; mt++) {
            const int r = mt * 16 + g;
            *(float2*)(dst + (size_t)(m0 + r) * 256 + c0) =
                make_float2(d[mt][nt][0] + bb0, d[mt][nt][1] + bb1);
            *(float2*)(dst + (size_t)(m0 + r + 8) * 256 + c0) =
                make_float2(d[mt][nt][2] + bb0, d[mt][nt][3] + bb1);
        }
    }
}

// ============================================================================
// K3c fold: 2 patches/block, 512 threads, occ 2, bf16 MMA; B via fragment-
// major LDG.64, A per-half rebuild + scalar LDS. fold1c/2c exact fp32.
// ============================================================================
__global__ __launch_bounds__(512, 2)
void fold_kernel(const float* __restrict__ grid_,
                 const float* __restrict__ Wf1a,
                 const float* __restrict__ bf1b,
                 const float* __restrict__ Wf1c, const float* __restrict__ bf1c,
                 const float* __restrict__ Wf2a,
                 const float* __restrict__ bf2b,
                 const float* __restrict__ Wf2c, const float* __restrict__ bf2c,
                 float* __restrict__ out)
{
    extern __shared__ float s[];
    __nv_bfloat16* hfA = (__nv_bfloat16*)s;        // [64][136] bf16 = 4352 fl
    float* hf2         = s + 4352;                 // [64 r][132] f32 = 8448 fl
    float* Wc1         = s + 12800;                // [384]
    float* Wc2         = s + 13184;                // [384]
    float* gx          = s + 13568;                // [32]
    float* gy          = s + 13600;                // [32]
    float* fv          = s + 13632;                // [192]
    float* cm          = s + 13824;                // [8] -> 13832 fl = 55328 B

    const int t = threadIdx.x;
    const int m0 = blockIdx.x * 2;
    const float scale = sqrtf(__uint_as_float(g_scale_bits));

    const int kp   = t & 63;       // k-pair within half
    const int rgrp = t >> 6;       // rows rgrp*8..+7
    const int pA   = rgrp >> 2;    // patch

    if (t < 384) { Wc1[t] = Wf1c[t]; Wc2[t] = Wf2c[t]; }
    if (t < 32) { gx[t] = grid_[2 * t]; gy[t] = grid_[2 * t + 1]; }
    if (t < 6)  cm[t] = g_cmean[(size_t)m0 * 3 + t];
    __syncthreads();

    const int lane = t & 31, g = lane >> 2, tig = lane & 3;
    const int wb = (t >> 5) * 8;               // warp's 8-column strip
    const int jw = t >> 5;                     // warp's n8 group (0..15)

    unsigned* h1w = (unsigned*)hfA;            // word view, stride 68

    #pragma unroll
    for (int stagei = 0; stagei < 2; stagei++) {
        const unsigned* Wp = stagei ? g_W2bp : g_W1bp;
        const float* bv = stagei ? bf2b : bf1b;

        float d[4][4];
        #pragma unroll
        for (int mt = 0; mt < 4; mt++)
            #pragma unroll
            for (int j = 0; j < 4; j++) d[mt][j] = 0.0f;

        #pragma unroll
        for (int h = 0; h < 2; h++) {
            // rebuild A for half h (packed bf16x2 stores)
            if (h) __syncthreads();            // prior half's MMA reads done
            {
                const int kg = h * 128 + 2 * kp;
                if (stagei == 0) {
                    const float2 bb = *(const float2*)(g_base1 + (size_t)(m0 + pA) * 256 + kg);
                    const float2 w0 = *(const float2*)(Wf1a + 256 * 256 + kg);
                    const float2 w1 = *(const float2*)(Wf1a + 257 * 256 + kg);
                    #pragma unroll
                    for (int i = 0; i < 8; i++) {
                        const int r  = rgrp * 8 + i;
                        const int rr = r & 31;
                        const float v0 = fmaxf(bb.x + gx[rr] * w0.x + gy[rr] * w1.x, 0.0f);
                        const float v1 = fmaxf(bb.y + gx[rr] * w0.y + gy[rr] * w1.y, 0.0f);
                        h1w[r * 68 + kp] = pack_bf16x2(v0, v1);
                    }
                } else {
                    const float2 bb = *(const float2*)(g_base2 + (size_t)(m0 + pA) * 256 + kg);
                    const float2 w0 = *(const float2*)(Wf2a + 256 * 256 + kg);
                    const float2 w1 = *(const float2*)(Wf2a + 257 * 256 + kg);
                    const float2 w2 = *(const float2*)(Wf2a + 258 * 256 + kg);
                    #pragma unroll
                    for (int i = 0; i < 8; i++) {
                        const int r = rgrp * 8 + i;
                        const float f0 = fv[r * 3], f1 = fv[r * 3 + 1], f2 = fv[r * 3 + 2];
                        const float v0 = fmaxf(bb.x + f0 * w0.x + f1 * w1.x + f2 * w2.x, 0.0f);
                        const float v1 = fmaxf(bb.y + f0 * w0.y + f1 * w1.y + f2 * w2.y, 0.0f);
                        h1w[r * 68 + kp] = pack_bf16x2(v0, v1);
                    }
                }
            }
            __syncthreads();                   // A ready

            // 8 k16-steps over this half; B fragment-major LDG.64
            #pragma unroll 2
            for (int ks = 0; ks < 8; ks++) {
                const int sfull = h * 8 + ks;          // global k16-step
                const uint2 bb = *(const uint2*)(Wp +
                    (((size_t)(sfull * 16 + jw) * 32 + lane) * 2));
                #pragma unroll
                for (int mt = 0; mt < 4; mt++) {
                    const unsigned* ap = h1w + (mt * 16 + g) * 68 + ks * 8 + tig;
                    unsigned a[4];
                    a[0] = ap[0];
                    a[1] = ap[8 * 68];
                    a[2] = ap[4];
                    a[3] = ap[8 * 68 + 4];
                    mma_bf16(d[mt], a, bb.x, bb.y);
                }
            }
        }

        // epilogue: bias + relu -> hf2[64 r][132]  (exact fp32)
        {
            const int col = wb + 2 * tig;
            const float bb0 = bv[col], bb1 = bv[col + 1];
            #pragma unroll
            for (int mt = 0; mt < 4; mt++) {
                const int r = mt * 16 + g;
                *(float2*)(hf2 + r * 132 + col) =
                    make_float2(fmaxf(d[mt][0] + bb0, 0.0f),
                                fmaxf(d[mt][1] + bb1, 0.0f));
                *(float2*)(hf2 + (r + 8) * 132 + col) =
                    make_float2(fmaxf(d[mt][2] + bb0, 0.0f),
                                fmaxf(d[mt][3] + bb1, 0.0f));
            }
        }
        __syncthreads();

        if (stagei == 0) {
            // fold1c: fv[r][q] = hf2[r]·Wf1c[:,q] + bf1c[q]  (exact fp32)
            if (t < 192) {
                const int r = t / 3, q = t - (t / 3) * 3;
                float acc = bf1c[q];
                #pragma unroll 8
                for (int k = 0; k < 128; k++) acc += hf2[r * 132 + k] * Wc1[k * 3 + q];
                fv[t] = acc;
            }
            __syncthreads();
        } else {
            // fold2c + output (exact fp32)
            if (t < 192) {
                const int r = t / 3, q = t - (t / 3) * 3;
                const int p = r >> 5, rr = r & 31;
                float acc = bf2c[q];
                #pragma unroll 8
                for (int k = 0; k < 128; k++) acc += hf2[r * 132 + k] * Wc2[k * 3 + q];
                out[(size_t)(m0 + p) * 96 + rr * 3 + q] = acc * scale + cm[p * 3 + q];
            }
        }
    }
}

// ============================================================================
extern "C" void kernel_launch(void* const* d_in, const int* in_sizes, int n_in,
                              void* d_out, int out_size)
{
    (void)in_sizes; (void)n_in; (void)out_size;
    const float* data = (const float*)d_in[0];
    const int*   perm = (const int*)  d_in[1];
    const float* grid = (const float*)d_in[2];
    const float* We1  = (const float*)d_in[3];
    const float* be1  = (const float*)d_in[4];
    const float* We2  = (const float*)d_in[5];
    const float* be2  = (const float*)d_in[6];
    const float* Wf1a = (const float*)d_in[7];
    const float* bf1a = (const float*)d_in[8];
    const float* Wf1b = (const float*)d_in[9];
    const float* bf1b = (const float*)d_in[10];
    const float* Wf1c = (const float*)d_in[11];
    const float* bf1c = (const float*)d_in[12];
    const float* Wf2a = (const float*)d_in[13];
    const float* bf2a = (const float*)d_in[14];
    const float* Wf2b = (const float*)d_in[15];
    const float* bf2b = (const float*)d_in[16];
    const float* Wf2c = (const float*)d_in[17];
    const float* bf2c = (const float*)d_in[18];
    float* out = (float*)d_out;

    const int fps_smem  = 3 * NN * sizeof(float);      // 98304
    const int knn_smem  = 3 * NN * sizeof(float);      // 98304
    const int enc_smem  = 4544  * sizeof(float);       // 18176
    const int base_smem = 8448  * sizeof(float);       // 33792
    const int fold_smem = 13832 * sizeof(float);       // 55328
    cudaFuncSetAttribute(fps_kernel,  cudaFuncAttributeMaxDynamicSharedMemorySize, fps_smem);
    cudaFuncSetAttribute(knn_kernel,  cudaFuncAttributeMaxDynamicSharedMemorySize, knn_smem);
    cudaFuncSetAttribute(enc_kernel,  cudaFuncAttributeMaxDynamicSharedMemorySize, enc_smem);
    cudaFuncSetAttribute(base_kernel, cudaFuncAttributeMaxDynamicSharedMemorySize, base_smem);
    cudaFuncSetAttribute(fold_kernel, cudaFuncAttributeMaxDynamicSharedMemorySize, fold_smem);

    pack_kernel<<<dim3(128, 5), 256>>>(We2, Wf1a, Wf2a, Wf1b, Wf2b);
    fps_kernel <<<BB, 1024, fps_smem>>>(data);
    knn_kernel <<<(BB * NC) / 8, 256, knn_smem>>>(data, perm);
    enc_kernel <<<MTOT / 2, 256, enc_smem>>>(We1, be1, be2);
    base_kernel<<<dim3(MTOT / 64, 2), 256, base_smem>>>(bf1a, bf2a);
    fold_kernel<<<MTOT / 2, 512, fold_smem>>>(grid, Wf1a, bf1b, Wf1c, bf1c,
                                              Wf2a, bf2b, Wf2c, bf2c, out);
}